// round 3
// baseline (speedup 1.0000x reference)
#include <cuda_runtime.h>

// actor_53781580480512 R3: f32x2-packed micro-MLP (pack 2 adjacent zp per thread)
//   B=4096, Z=64, P=4096, H=4
// Folding of LN affine params into W2/W3 as in R2 (fold_kernel).
// Main kernel: each thread owns p=(z, 2*lane) and p+1, packs the two
// elements into f32x2 registers; all FMA-class math is fma.rn.f32x2
// (FFMA2 SASS); tanh/rsqrt via scalar MUFU.

#define ZDIM 64
#define PDIM 4096
#define BTILE 128

__device__ float g_W2f[PDIM * 16];
__device__ float g_b2f[PDIM * 4];
__device__ float g_W3f[PDIM * 4];
__device__ float g_b3f[PDIM];

typedef unsigned long long f2;   // packed f32x2

__device__ __forceinline__ f2 pack2(float lo, float hi) {
    f2 r; asm("mov.b64 %0, {%1, %2};" : "=l"(r) : "f"(lo), "f"(hi)); return r;
}
__device__ __forceinline__ void unpack2(f2 v, float& lo, float& hi) {
    asm("mov.b64 {%0, %1}, %2;" : "=f"(lo), "=f"(hi) : "l"(v));
}
__device__ __forceinline__ f2 fma2(f2 a, f2 b, f2 c) {
    f2 r; asm("fma.rn.f32x2 %0, %1, %2, %3;" : "=l"(r) : "l"(a), "l"(b), "l"(c)); return r;
}
__device__ __forceinline__ f2 add2(f2 a, f2 b) {
    f2 r; asm("add.rn.f32x2 %0, %1, %2;" : "=l"(r) : "l"(a), "l"(b)); return r;
}
__device__ __forceinline__ f2 mul2(f2 a, f2 b) {
    f2 r; asm("mul.rn.f32x2 %0, %1, %2;" : "=l"(r) : "l"(a), "l"(b)); return r;
}
__device__ __forceinline__ float tanh_mufu(float x) {
    float y; asm("tanh.approx.f32 %0, %1;" : "=f"(y) : "f"(x)); return y;
}
__device__ __forceinline__ f2 tanh2(f2 v) {
    float lo, hi; unpack2(v, lo, hi);
    return pack2(tanh_mufu(lo), tanh_mufu(hi));
}
__device__ __forceinline__ f2 rsqrt2(f2 v) {
    float lo, hi; unpack2(v, lo, hi);
    return pack2(rsqrtf(lo), rsqrtf(hi));
}

__global__ void fold_kernel(
    const float* __restrict__ g1, const float* __restrict__ be1,
    const float* __restrict__ W2, const float* __restrict__ b2,
    const float* __restrict__ g2, const float* __restrict__ be2,
    const float* __restrict__ W3, const float* __restrict__ b3)
{
    int p = blockIdx.x * blockDim.x + threadIdx.x;
    if (p >= PDIM) return;
    float gg1[4], bbe1[4];
#pragma unroll
    for (int i = 0; i < 4; i++) { gg1[i] = g1[p*4+i]; bbe1[i] = be1[p*4+i]; }
#pragma unroll
    for (int j = 0; j < 4; j++) {
        float acc = b2[p*4+j];
#pragma unroll
        for (int i = 0; i < 4; i++) {
            float w = W2[p*16 + i*4 + j];
            g_W2f[p*16 + i*4 + j] = gg1[i] * w;
            acc = fmaf(bbe1[i], w, acc);
        }
        g_b2f[p*4+j] = acc;
    }
    float acc3 = b3[p];
#pragma unroll
    for (int j = 0; j < 4; j++) {
        float w = W3[p*4+j];
        g_W3f[p*4+j] = g2[p*4+j] * w;
        acc3 = fmaf(be2[p*4+j], w, acc3);
    }
    g_b3f[p] = acc3;
}

__global__ __launch_bounds__(256, 2)
void actor_mlp_kernel(
    const float* __restrict__ x,
    const float* __restrict__ W1, const float* __restrict__ b1,
    float* __restrict__ out, int B)
{
    const int lane = threadIdx.x & 31;      // zp-pair index: zp = 2*lane
    const int bl   = threadIdx.x >> 5;      // 0..7
    const int z    = blockIdx.x;            // 0..63
    const int b0   = blockIdx.y * BTILE + bl;
    const int p0   = z * ZDIM + 2 * lane;   // even p
    const int p1   = p0 + 1;

    // ---- packed per-(p0,p1) weights ----
    f2 w1x[8], bb1x[4], w2x[16], bb2x[4], w3x[4];
#pragma unroll
    for (int i = 0; i < 8; i++)
        w1x[i] = pack2(__ldg(&W1[p0 * 8 + i]), __ldg(&W1[p1 * 8 + i]));
#pragma unroll
    for (int i = 0; i < 4; i++)
        bb1x[i] = pack2(__ldg(&b1[p0 * 4 + i]), __ldg(&b1[p1 * 4 + i]));
#pragma unroll
    for (int i = 0; i < 16; i++)
        w2x[i] = pack2(g_W2f[p0 * 16 + i], g_W2f[p1 * 16 + i]);
#pragma unroll
    for (int i = 0; i < 4; i++) {
        bb2x[i] = pack2(g_b2f[p0 * 4 + i], g_b2f[p1 * 4 + i]);
        w3x[i]  = pack2(g_W3f[p0 * 4 + i], g_W3f[p1 * 4 + i]);
    }
    const f2 bb3x = pack2(g_b3f[p0], g_b3f[p1]);

    const f2 cNQ  = pack2(-0.25f, -0.25f);
    const f2 cQ   = pack2(0.25f, 0.25f);
    const f2 cEps = pack2(1e-5f, 1e-5f);
    const f2 cH   = pack2(0.5f, 0.5f);

#pragma unroll 2
    for (int it = 0; it < BTILE / 8; it++) {
        const int b = b0 + 8 * it;

        const float xa = __ldg(&x[b * ZDIM + z]);               // warp-uniform
        const float2 xcv = __ldg((const float2*)&x[b * ZDIM + 2 * lane]); // LDG.64
        const f2 xa2 = pack2(xa, xa);
        const f2 xc2 = pack2(xcv.x, xcv.y);

        // layer 1 + tanh
        f2 h[4];
#pragma unroll
        for (int j = 0; j < 4; j++)
            h[j] = tanh2(fma2(xa2, w1x[j], fma2(xc2, w1x[4 + j], bb1x[j])));

        // LN1 stats
        f2 sum  = add2(add2(h[0], h[1]), add2(h[2], h[3]));
        f2 negm = mul2(sum, cNQ);
        f2 d0 = add2(h[0], negm), d1 = add2(h[1], negm);
        f2 d2 = add2(h[2], negm), d3 = add2(h[3], negm);
        f2 v  = fma2(d0, d0, fma2(d1, d1, fma2(d2, d2, mul2(d3, d3))));
        f2 r  = rsqrt2(fma2(v, cQ, cEps));

        // layer 2 + tanh
        f2 k[4];
#pragma unroll
        for (int j = 0; j < 4; j++) {
            f2 dot = mul2(d0, w2x[j]);
            dot = fma2(d1, w2x[4 + j], dot);
            dot = fma2(d2, w2x[8 + j], dot);
            dot = fma2(d3, w2x[12 + j], dot);
            k[j] = tanh2(fma2(r, dot, bb2x[j]));
        }

        // LN2 stats
        f2 sum2  = add2(add2(k[0], k[1]), add2(k[2], k[3]));
        f2 negm2 = mul2(sum2, cNQ);
        f2 e0 = add2(k[0], negm2), e1 = add2(k[1], negm2);
        f2 e2 = add2(k[2], negm2), e3 = add2(k[3], negm2);
        f2 v2 = fma2(e0, e0, fma2(e1, e1, fma2(e2, e2, mul2(e3, e3))));
        f2 r2 = rsqrt2(fma2(v2, cQ, cEps));

        // layer 3 + sigmoid(x) = 0.5*tanh(0.5x)+0.5
        f2 dot3 = mul2(e0, w3x[0]);
        dot3 = fma2(e1, w3x[1], dot3);
        dot3 = fma2(e2, w3x[2], dot3);
        dot3 = fma2(e3, w3x[3], dot3);
        f2 pre = fma2(r2, dot3, bb3x);
        f2 o   = fma2(tanh2(mul2(pre, cH)), cH, cH);

        float olo, ohi; unpack2(o, olo, ohi);
        *(float2*)&out[b * PDIM + p0] = make_float2(olo, ohi);  // STG.64
    }
}

extern "C" void kernel_launch(void* const* d_in, const int* in_sizes, int n_in,
                              void* d_out, int out_size)
{
    const float* x   = (const float*)d_in[0];
    const float* W1  = (const float*)d_in[1];
    const float* b1  = (const float*)d_in[2];
    const float* g1  = (const float*)d_in[3];
    const float* be1 = (const float*)d_in[4];
    const float* W2  = (const float*)d_in[5];
    const float* b2  = (const float*)d_in[6];
    const float* g2  = (const float*)d_in[7];
    const float* be2 = (const float*)d_in[8];
    const float* W3  = (const float*)d_in[9];
    const float* b3  = (const float*)d_in[10];
    float* out = (float*)d_out;

    int B = in_sizes[0] / ZDIM;

    fold_kernel<<<PDIM / 256, 256>>>(g1, be1, W2, b2, g2, be2, W3, b3);

    dim3 grid(ZDIM, (B + BTILE - 1) / BTILE);   // 64 x 32
    actor_mlp_kernel<<<grid, 256>>>(x, W1, b1, out, B);
}

// round 4
// speedup vs baseline: 2.9376x; 2.9376x over previous
#include <cuda_runtime.h>
#include <cuda_fp16.h>

// actor_53781580480512 R4: half2-packed micro-MLP (pack 2 b-elements per thread)
//   B=4096, Z=64, P=4096, H=4
// Layer 1 in f32 (exact inputs + MUFU tanh f32), then h packed to half2;
// LN1/L2/LN2/L3 in HFMA2 with duplicated half2 weights (1 reg per weight,
// same register budget as scalar). tanh.approx.f16x2 / rsqrt f16x2 for the
// packed transcendentals. LN affine params folded into W2/W3 (fold_kernel).

#define ZDIM 64
#define PDIM 4096
#define BTILE 128

__device__ __half2 g_W2h[PDIM * 16];  // (g1*W2) duplicated
__device__ __half2 g_b2h[PDIM * 4];   // b2 + be1@W2 duplicated
__device__ __half2 g_W3h[PDIM * 4];   // (g2*W3) duplicated
__device__ __half2 g_b3h[PDIM];       // b3 + be2.W3 duplicated

__device__ __forceinline__ float tanh_mufu(float x) {
    float y; asm("tanh.approx.f32 %0, %1;" : "=f"(y) : "f"(x)); return y;
}
__device__ __forceinline__ __half2 tanh2(__half2 v) {
    unsigned vi = *reinterpret_cast<unsigned*>(&v), ri;
    asm("tanh.approx.f16x2 %0, %1;" : "=r"(ri) : "r"(vi));
    return *reinterpret_cast<__half2*>(&ri);
}

__global__ void fold_kernel(
    const float* __restrict__ g1, const float* __restrict__ be1,
    const float* __restrict__ W2, const float* __restrict__ b2,
    const float* __restrict__ g2, const float* __restrict__ be2,
    const float* __restrict__ W3, const float* __restrict__ b3)
{
    int p = blockIdx.x * blockDim.x + threadIdx.x;
    if (p >= PDIM) return;
    float gg1[4], bbe1[4];
#pragma unroll
    for (int i = 0; i < 4; i++) { gg1[i] = g1[p*4+i]; bbe1[i] = be1[p*4+i]; }
#pragma unroll
    for (int j = 0; j < 4; j++) {
        float acc = b2[p*4+j];
#pragma unroll
        for (int i = 0; i < 4; i++) {
            float w = W2[p*16 + i*4 + j];
            g_W2h[p*16 + i*4 + j] = __float2half2_rn(gg1[i] * w);
            acc = fmaf(bbe1[i], w, acc);
        }
        g_b2h[p*4+j] = __float2half2_rn(acc);
    }
    float acc3 = b3[p];
#pragma unroll
    for (int j = 0; j < 4; j++) {
        float w = W3[p*4+j];
        g_W3h[p*4+j] = __float2half2_rn(g2[p*4+j] * w);
        acc3 = fmaf(be2[p*4+j], w, acc3);
    }
    g_b3h[p] = __float2half2_rn(acc3);
}

__global__ __launch_bounds__(256, 3)
void actor_mlp_kernel(
    const float* __restrict__ x,
    const float* __restrict__ W1, const float* __restrict__ b1,
    float* __restrict__ out, int B)
{
    const int zp = threadIdx.x & 63;        // 0..63
    const int bl = threadIdx.x >> 6;        // 0..3
    const int z  = blockIdx.x;              // 0..63
    const int b0 = blockIdx.y * BTILE;
    const int p  = z * ZDIM + zp;

    // ---- per-p weights: f32 layer-1, half2 (duplicated) rest : 37 regs ----
    float w1[8];
#pragma unroll
    for (int i = 0; i < 8; i++) w1[i] = __ldg(&W1[p * 8 + i]);
    float bb1[4];
#pragma unroll
    for (int i = 0; i < 4; i++) bb1[i] = __ldg(&b1[p * 4 + i]);
    __half2 w2h[16], bb2h[4], w3h[4];
#pragma unroll
    for (int i = 0; i < 16; i++) w2h[i] = g_W2h[p * 16 + i];
#pragma unroll
    for (int i = 0; i < 4; i++) {
        bb2h[i] = g_b2h[p * 4 + i];
        w3h[i]  = g_W3h[p * 4 + i];
    }
    const __half2 bb3h = g_b3h[p];

    const __half2 cNQ  = __float2half2_rn(-0.25f);
    const __half2 cQ   = __float2half2_rn(0.25f);
    const __half2 cEps = __float2half2_rn(1e-5f);
    const __half2 cH   = __float2half2_rn(0.5f);

    // each thread processes b-pairs (b, b+1); 16 iterations
#pragma unroll 1
    for (int it = 0; it < BTILE / 8; it++) {
        const int b = b0 + 2 * bl + 8 * it;

        const float xa0 = __ldg(&x[b * ZDIM + z]);          // uniform
        const float xa1 = __ldg(&x[(b + 1) * ZDIM + z]);
        const float xc0 = __ldg(&x[b * ZDIM + zp]);         // coalesced
        const float xc1 = __ldg(&x[(b + 1) * ZDIM + zp]);

        // ---- layer 1 + tanh in f32, pack to half2 ----
        __half2 h[4];
#pragma unroll
        for (int j = 0; j < 4; j++) {
            float u0 = tanh_mufu(fmaf(xa0, w1[j], fmaf(xc0, w1[4 + j], bb1[j])));
            float u1 = tanh_mufu(fmaf(xa1, w1[j], fmaf(xc1, w1[4 + j], bb1[j])));
            h[j] = __floats2half2_rn(u0, u1);
        }

        // ---- LN1 (half2) ----
        __half2 sum = __hadd2(__hadd2(h[0], h[1]), __hadd2(h[2], h[3]));
        __half2 nm  = __hmul2(sum, cNQ);                    // -mean
        __half2 d0 = __hadd2(h[0], nm), d1 = __hadd2(h[1], nm);
        __half2 d2 = __hadd2(h[2], nm), d3 = __hadd2(h[3], nm);
        __half2 v = __hfma2(d0, d0, __hfma2(d1, d1, __hfma2(d2, d2, __hmul2(d3, d3))));
        __half2 r = h2rsqrt(__hfma2(v, cQ, cEps));

        // ---- layer 2 + tanh (half2) ----
        __half2 k[4];
#pragma unroll
        for (int j = 0; j < 4; j++) {
            __half2 dot = __hmul2(d0, w2h[j]);
            dot = __hfma2(d1, w2h[4 + j], dot);
            dot = __hfma2(d2, w2h[8 + j], dot);
            dot = __hfma2(d3, w2h[12 + j], dot);
            k[j] = tanh2(__hfma2(r, dot, bb2h[j]));
        }

        // ---- LN2 (half2) ----
        __half2 sum2 = __hadd2(__hadd2(k[0], k[1]), __hadd2(k[2], k[3]));
        __half2 nm2  = __hmul2(sum2, cNQ);
        __half2 e0 = __hadd2(k[0], nm2), e1 = __hadd2(k[1], nm2);
        __half2 e2 = __hadd2(k[2], nm2), e3 = __hadd2(k[3], nm2);
        __half2 v2 = __hfma2(e0, e0, __hfma2(e1, e1, __hfma2(e2, e2, __hmul2(e3, e3))));
        __half2 r2 = h2rsqrt(__hfma2(v2, cQ, cEps));

        // ---- layer 3 + sigmoid(x)=0.5*tanh(0.5x)+0.5 (half2) ----
        __half2 dot3 = __hmul2(e0, w3h[0]);
        dot3 = __hfma2(e1, w3h[1], dot3);
        dot3 = __hfma2(e2, w3h[2], dot3);
        dot3 = __hfma2(e3, w3h[3], dot3);
        __half2 pre = __hfma2(r2, dot3, bb3h);
        __half2 o   = __hfma2(tanh2(__hmul2(pre, cH)), cH, cH);

        float2 of = __half22float2(o);
        out[b * PDIM + p]       = of.x;
        out[(b + 1) * PDIM + p] = of.y;
    }
}

extern "C" void kernel_launch(void* const* d_in, const int* in_sizes, int n_in,
                              void* d_out, int out_size)
{
    const float* x   = (const float*)d_in[0];
    const float* W1  = (const float*)d_in[1];
    const float* b1  = (const float*)d_in[2];
    const float* g1  = (const float*)d_in[3];
    const float* be1 = (const float*)d_in[4];
    const float* W2  = (const float*)d_in[5];
    const float* b2  = (const float*)d_in[6];
    const float* g2  = (const float*)d_in[7];
    const float* be2 = (const float*)d_in[8];
    const float* W3  = (const float*)d_in[9];
    const float* b3  = (const float*)d_in[10];
    float* out = (float*)d_out;

    int B = in_sizes[0] / ZDIM;

    fold_kernel<<<PDIM / 256, 256>>>(g1, be1, W2, b2, g2, be2, W3, b3);

    dim3 grid(ZDIM, (B + BTILE - 1) / BTILE);   // 64 x 32
    actor_mlp_kernel<<<grid, 256>>>(x, W1, b1, out, B);
}

// round 5
// speedup vs baseline: 3.6737x; 1.2506x over previous
#include <cuda_runtime.h>
#include <cuda_fp16.h>

// actor_53781580480512 R5: half2 micro-MLP, ILP=2 chains (4 b-elems/thread/iter),
// fold merged into main kernel prologue (single launch).
//   B=4096, Z=64, P=4096, H=4
// Folded weights (computed per-thread in prologue):
//   w2f[i][j] = 2*g1[i]*W2[i][j]   (2 from rsqrt(0.25s+e)=2*rsqrt(s+4e))
//   b2f[j]    = b2[j] + sum_i be1[i]*W2[i][j]
//   w3f[j]    = 2*g2[j]*W3[j]
//   b3f       = b3 + sum_j be2[j]*W3[j]

#define ZDIM 64
#define PDIM 4096
#define BTILE 128

__device__ __forceinline__ __half2 tanh2(__half2 v) {
    unsigned vi = *reinterpret_cast<unsigned*>(&v), ri;
    asm("tanh.approx.f16x2 %0, %1;" : "=r"(ri) : "r"(vi));
    return *reinterpret_cast<__half2*>(&ri);
}

__global__ __launch_bounds__(256, 2)
void actor_mlp_kernel(
    const float* __restrict__ x,
    const float* __restrict__ W1, const float* __restrict__ b1,
    const float* __restrict__ g1, const float* __restrict__ be1,
    const float* __restrict__ W2, const float* __restrict__ b2,
    const float* __restrict__ g2, const float* __restrict__ be2,
    const float* __restrict__ W3, const float* __restrict__ b3,
    float* __restrict__ out, int B)
{
    const int zp = threadIdx.x & 63;        // 0..63
    const int bl = threadIdx.x >> 6;        // 0..3
    const int z  = blockIdx.x;              // 0..63
    const int b0 = blockIdx.y * BTILE;
    const int p  = z * ZDIM + zp;

    // ================= prologue: load + fold (once per 32 b-values) =========
    float w1[8];
    {
        float4 a = __ldg((const float4*)&W1[p * 8]);
        float4 bq = __ldg((const float4*)&W1[p * 8 + 4]);
        w1[0]=a.x; w1[1]=a.y; w1[2]=a.z; w1[3]=a.w;
        w1[4]=bq.x; w1[5]=bq.y; w1[6]=bq.z; w1[7]=bq.w;
    }
    float bb1[4];
    {
        float4 a = __ldg((const float4*)&b1[p * 4]);
        bb1[0]=a.x; bb1[1]=a.y; bb1[2]=a.z; bb1[3]=a.w;
    }

    __half2 w2h[16], bb2h[4], w3h[4], bb3h;
    {
        float4 g1v  = __ldg((const float4*)&g1 [p * 4]);
        float4 be1v = __ldg((const float4*)&be1[p * 4]);
        float gg1[4]  = {2.0f*g1v.x, 2.0f*g1v.y, 2.0f*g1v.z, 2.0f*g1v.w};
        float bbe1[4] = {be1v.x, be1v.y, be1v.z, be1v.w};
        float4 b2v = __ldg((const float4*)&b2[p * 4]);
        float b2f[4] = {b2v.x, b2v.y, b2v.z, b2v.w};
#pragma unroll
        for (int i = 0; i < 4; i++) {
            float4 wr = __ldg((const float4*)&W2[p * 16 + i * 4]);
            float wrow[4] = {wr.x, wr.y, wr.z, wr.w};
#pragma unroll
            for (int j = 0; j < 4; j++) {
                w2h[i * 4 + j] = __float2half2_rn(gg1[i] * wrow[j]);
                b2f[j] = fmaf(bbe1[i], wrow[j], b2f[j]);
            }
        }
#pragma unroll
        for (int j = 0; j < 4; j++) bb2h[j] = __float2half2_rn(b2f[j]);

        float4 g2v  = __ldg((const float4*)&g2 [p * 4]);
        float4 be2v = __ldg((const float4*)&be2[p * 4]);
        float4 w3v  = __ldg((const float4*)&W3 [p * 4]);
        w3h[0] = __float2half2_rn(2.0f * g2v.x * w3v.x);
        w3h[1] = __float2half2_rn(2.0f * g2v.y * w3v.y);
        w3h[2] = __float2half2_rn(2.0f * g2v.z * w3v.z);
        w3h[3] = __float2half2_rn(2.0f * g2v.w * w3v.w);
        float b3f = __ldg(&b3[p]);
        b3f = fmaf(be2v.x, w3v.x, b3f);
        b3f = fmaf(be2v.y, w3v.y, b3f);
        b3f = fmaf(be2v.z, w3v.z, b3f);
        b3f = fmaf(be2v.w, w3v.w, b3f);
        bb3h = __float2half2_rn(b3f);
    }

    const __half2 cNQ   = __float2half2_rn(-0.25f);
    const __half2 cEps4 = __float2half2_rn(4e-5f);   // 4*eps (rsqrt folding)
    const __half2 cH    = __float2half2_rn(0.5f);

    // ============ main loop: 4 b-elements per thread per iteration ==========
#pragma unroll 1
    for (int it = 0; it < BTILE / 16; it++) {        // 8 iterations
        const int b = b0 + 4 * bl + 16 * it;

        float xa[4], xc[4];
#pragma unroll
        for (int u = 0; u < 4; u++) {
            xa[u] = __ldg(&x[(b + u) * ZDIM + z]);   // warp-uniform
            xc[u] = __ldg(&x[(b + u) * ZDIM + zp]);  // coalesced
        }

        float o[4];
#pragma unroll
        for (int u = 0; u < 2; u++) {                // 2 independent chains
            const float xa0 = xa[2*u], xa1 = xa[2*u+1];
            const float xc0 = xc[2*u], xc1 = xc[2*u+1];

            // layer 1 in f32, packed tanh
            __half2 h[4];
#pragma unroll
            for (int j = 0; j < 4; j++) {
                float u0 = fmaf(xa0, w1[j], fmaf(xc0, w1[4 + j], bb1[j]));
                float u1 = fmaf(xa1, w1[j], fmaf(xc1, w1[4 + j], bb1[j]));
                h[j] = tanh2(__floats2half2_rn(u0, u1));
            }

            // LN1 (affine folded; rsqrt 2x folded into w2h)
            __half2 sum = __hadd2(__hadd2(h[0], h[1]), __hadd2(h[2], h[3]));
            __half2 nm  = __hmul2(sum, cNQ);
            __half2 d0 = __hadd2(h[0], nm), d1 = __hadd2(h[1], nm);
            __half2 d2 = __hadd2(h[2], nm), d3 = __hadd2(h[3], nm);
            __half2 v = __hfma2(d0, d0, __hfma2(d1, d1, __hfma2(d2, d2, __hmul2(d3, d3))));
            __half2 r = h2rsqrt(__hadd2(v, cEps4));

            // layer 2 + tanh
            __half2 k[4];
#pragma unroll
            for (int j = 0; j < 4; j++) {
                __half2 dot = __hmul2(d0, w2h[j]);
                dot = __hfma2(d1, w2h[4 + j], dot);
                dot = __hfma2(d2, w2h[8 + j], dot);
                dot = __hfma2(d3, w2h[12 + j], dot);
                k[j] = tanh2(__hfma2(r, dot, bb2h[j]));
            }

            // LN2
            __half2 sum2 = __hadd2(__hadd2(k[0], k[1]), __hadd2(k[2], k[3]));
            __half2 nm2  = __hmul2(sum2, cNQ);
            __half2 e0 = __hadd2(k[0], nm2), e1 = __hadd2(k[1], nm2);
            __half2 e2 = __hadd2(k[2], nm2), e3 = __hadd2(k[3], nm2);
            __half2 v2 = __hfma2(e0, e0, __hfma2(e1, e1, __hfma2(e2, e2, __hmul2(e3, e3))));
            __half2 r2 = h2rsqrt(__hadd2(v2, cEps4));

            // layer 3 + sigmoid(x)=0.5*tanh(0.5x)+0.5
            __half2 dot3 = __hmul2(e0, w3h[0]);
            dot3 = __hfma2(e1, w3h[1], dot3);
            dot3 = __hfma2(e2, w3h[2], dot3);
            dot3 = __hfma2(e3, w3h[3], dot3);
            __half2 pre = __hfma2(r2, dot3, bb3h);
            __half2 og  = __hfma2(tanh2(__hmul2(pre, cH)), cH, cH);

            float2 of = __half22float2(og);
            o[2*u] = of.x; o[2*u+1] = of.y;
        }

#pragma unroll
        for (int u = 0; u < 4; u++)
            out[(b + u) * PDIM + p] = o[u];
    }
}

extern "C" void kernel_launch(void* const* d_in, const int* in_sizes, int n_in,
                              void* d_out, int out_size)
{
    const float* x   = (const float*)d_in[0];
    const float* W1  = (const float*)d_in[1];
    const float* b1  = (const float*)d_in[2];
    const float* g1  = (const float*)d_in[3];
    const float* be1 = (const float*)d_in[4];
    const float* W2  = (const float*)d_in[5];
    const float* b2  = (const float*)d_in[6];
    const float* g2  = (const float*)d_in[7];
    const float* be2 = (const float*)d_in[8];
    const float* W3  = (const float*)d_in[9];
    const float* b3  = (const float*)d_in[10];
    float* out = (float*)d_out;

    int B = in_sizes[0] / ZDIM;
    dim3 grid(ZDIM, (B + BTILE - 1) / BTILE);   // 64 x 32
    actor_mlp_kernel<<<grid, 256>>>(x, W1, b1, g1, be1, W2, b2, g2, be2,
                                    W3, b3, out, B);
}

// round 6
// speedup vs baseline: 4.2824x; 1.1657x over previous
#include <cuda_runtime.h>
#include <cuda_fp16.h>

// actor_53781580480512 R6: all-half2 micro-MLP (layer 1 now HFMA2 too),
// ILP=2 chains (4 b-elems/thread/iter), inline fold, single launch.
//   B=4096, Z=64, P=4096, H=4
// Folds: LN affine into W2/W3; rsqrt(0.25s+eps)=2*rsqrt(s+4eps) with the
// 2x absorbed into w2h/w3h.

#define ZDIM 64
#define PDIM 4096
#define BTILE 128

__device__ __forceinline__ __half2 tanh2(__half2 v) {
    unsigned vi = *reinterpret_cast<unsigned*>(&v), ri;
    asm("tanh.approx.f16x2 %0, %1;" : "=r"(ri) : "r"(vi));
    return *reinterpret_cast<__half2*>(&ri);
}

__global__ __launch_bounds__(256, 2)
void actor_mlp_kernel(
    const float* __restrict__ x,
    const float* __restrict__ W1, const float* __restrict__ b1,
    const float* __restrict__ g1, const float* __restrict__ be1,
    const float* __restrict__ W2, const float* __restrict__ b2,
    const float* __restrict__ g2, const float* __restrict__ be2,
    const float* __restrict__ W3, const float* __restrict__ b3,
    float* __restrict__ out, int B)
{
    const int zp = threadIdx.x & 63;        // 0..63
    const int bl = threadIdx.x >> 6;        // 0..3
    const int z  = blockIdx.x;              // 0..63
    const int b0 = blockIdx.y * BTILE;
    const int p  = z * ZDIM + zp;

    // ================= prologue: load + fold + halve (once per 32 b) ========
    __half2 w1h[8], bb1h[4];
    {
        float4 a = __ldg((const float4*)&W1[p * 8]);
        float4 c = __ldg((const float4*)&W1[p * 8 + 4]);
        w1h[0]=__float2half2_rn(a.x); w1h[1]=__float2half2_rn(a.y);
        w1h[2]=__float2half2_rn(a.z); w1h[3]=__float2half2_rn(a.w);
        w1h[4]=__float2half2_rn(c.x); w1h[5]=__float2half2_rn(c.y);
        w1h[6]=__float2half2_rn(c.z); w1h[7]=__float2half2_rn(c.w);
        float4 bv = __ldg((const float4*)&b1[p * 4]);
        bb1h[0]=__float2half2_rn(bv.x); bb1h[1]=__float2half2_rn(bv.y);
        bb1h[2]=__float2half2_rn(bv.z); bb1h[3]=__float2half2_rn(bv.w);
    }

    __half2 w2h[16], bb2h[4], w3h[4], bb3h;
    {
        float4 g1v  = __ldg((const float4*)&g1 [p * 4]);
        float4 be1v = __ldg((const float4*)&be1[p * 4]);
        float gg1[4]  = {2.0f*g1v.x, 2.0f*g1v.y, 2.0f*g1v.z, 2.0f*g1v.w};
        float bbe1[4] = {be1v.x, be1v.y, be1v.z, be1v.w};
        float4 b2v = __ldg((const float4*)&b2[p * 4]);
        float b2f[4] = {b2v.x, b2v.y, b2v.z, b2v.w};
#pragma unroll
        for (int i = 0; i < 4; i++) {
            float4 wr = __ldg((const float4*)&W2[p * 16 + i * 4]);
            float wrow[4] = {wr.x, wr.y, wr.z, wr.w};
#pragma unroll
            for (int j = 0; j < 4; j++) {
                w2h[i * 4 + j] = __float2half2_rn(gg1[i] * wrow[j]);
                b2f[j] = fmaf(bbe1[i], wrow[j], b2f[j]);
            }
        }
#pragma unroll
        for (int j = 0; j < 4; j++) bb2h[j] = __float2half2_rn(b2f[j]);

        float4 g2v  = __ldg((const float4*)&g2 [p * 4]);
        float4 be2v = __ldg((const float4*)&be2[p * 4]);
        float4 w3v  = __ldg((const float4*)&W3 [p * 4]);
        w3h[0] = __float2half2_rn(2.0f * g2v.x * w3v.x);
        w3h[1] = __float2half2_rn(2.0f * g2v.y * w3v.y);
        w3h[2] = __float2half2_rn(2.0f * g2v.z * w3v.z);
        w3h[3] = __float2half2_rn(2.0f * g2v.w * w3v.w);
        float b3f = __ldg(&b3[p]);
        b3f = fmaf(be2v.x, w3v.x, b3f);
        b3f = fmaf(be2v.y, w3v.y, b3f);
        b3f = fmaf(be2v.z, w3v.z, b3f);
        b3f = fmaf(be2v.w, w3v.w, b3f);
        bb3h = __float2half2_rn(b3f);
    }

    const __half2 cNQ   = __float2half2_rn(-0.25f);
    const __half2 cEps4 = __float2half2_rn(4e-5f);
    const __half2 cH    = __float2half2_rn(0.5f);

    // base pointers (pointer-increment addressing)
    const float* xpa = x + (b0 + 4 * bl) * ZDIM + z;
    const float* xpc = x + (b0 + 4 * bl) * ZDIM + zp;
    float*       opt = out + (b0 + 4 * bl) * PDIM + p;

    // ============ main loop: 4 b-elements per thread per iteration ==========
#pragma unroll 1
    for (int it = 0; it < BTILE / 16; it++) {        // 8 iterations
        float xa[4], xc[4];
#pragma unroll
        for (int u = 0; u < 4; u++) {
            xa[u] = __ldg(xpa + u * ZDIM);           // warp-uniform
            xc[u] = __ldg(xpc + u * ZDIM);           // coalesced
        }
        xpa += 16 * ZDIM; xpc += 16 * ZDIM;

        float o[4];
#pragma unroll
        for (int u = 0; u < 2; u++) {                // 2 independent chains
            __half2 xa2 = __floats2half2_rn(xa[2*u], xa[2*u+1]);
            __half2 xc2 = __floats2half2_rn(xc[2*u], xc[2*u+1]);

            // layer 1 + tanh (half2)
            __half2 h[4];
#pragma unroll
            for (int j = 0; j < 4; j++)
                h[j] = tanh2(__hfma2(xa2, w1h[j],
                             __hfma2(xc2, w1h[4 + j], bb1h[j])));

            // LN1 (affine + 2x rsqrt folded downstream)
            __half2 sum = __hadd2(__hadd2(h[0], h[1]), __hadd2(h[2], h[3]));
            __half2 nm  = __hmul2(sum, cNQ);
            __half2 d0 = __hadd2(h[0], nm), d1 = __hadd2(h[1], nm);
            __half2 d2 = __hadd2(h[2], nm), d3 = __hadd2(h[3], nm);
            __half2 v = __hfma2(d0, d0, __hfma2(d1, d1,
                        __hfma2(d2, d2, __hmul2(d3, d3))));
            __half2 r = h2rsqrt(__hadd2(v, cEps4));

            // layer 2 + tanh
            __half2 k[4];
#pragma unroll
            for (int j = 0; j < 4; j++) {
                __half2 dot = __hmul2(d0, w2h[j]);
                dot = __hfma2(d1, w2h[4 + j], dot);
                dot = __hfma2(d2, w2h[8 + j], dot);
                dot = __hfma2(d3, w2h[12 + j], dot);
                k[j] = tanh2(__hfma2(r, dot, bb2h[j]));
            }

            // LN2
            __half2 sum2 = __hadd2(__hadd2(k[0], k[1]), __hadd2(k[2], k[3]));
            __half2 nm2  = __hmul2(sum2, cNQ);
            __half2 e0 = __hadd2(k[0], nm2), e1 = __hadd2(k[1], nm2);
            __half2 e2 = __hadd2(k[2], nm2), e3 = __hadd2(k[3], nm2);
            __half2 v2 = __hfma2(e0, e0, __hfma2(e1, e1,
                         __hfma2(e2, e2, __hmul2(e3, e3))));
            __half2 r2 = h2rsqrt(__hadd2(v2, cEps4));

            // layer 3 + sigmoid(x)=0.5*tanh(0.5x)+0.5
            __half2 dot3 = __hmul2(e0, w3h[0]);
            dot3 = __hfma2(e1, w3h[1], dot3);
            dot3 = __hfma2(e2, w3h[2], dot3);
            dot3 = __hfma2(e3, w3h[3], dot3);
            __half2 pre = __hfma2(r2, dot3, bb3h);
            __half2 og  = __hfma2(tanh2(__hmul2(pre, cH)), cH, cH);

            float2 of = __half22float2(og);
            o[2*u] = of.x; o[2*u+1] = of.y;
        }

#pragma unroll
        for (int u = 0; u < 4; u++)
            opt[u * PDIM] = o[u];
        opt += 16 * PDIM;
    }
}

extern "C" void kernel_launch(void* const* d_in, const int* in_sizes, int n_in,
                              void* d_out, int out_size)
{
    const float* x   = (const float*)d_in[0];
    const float* W1  = (const float*)d_in[1];
    const float* b1  = (const float*)d_in[2];
    const float* g1  = (const float*)d_in[3];
    const float* be1 = (const float*)d_in[4];
    const float* W2  = (const float*)d_in[5];
    const float* b2  = (const float*)d_in[6];
    const float* g2  = (const float*)d_in[7];
    const float* be2 = (const float*)d_in[8];
    const float* W3  = (const float*)d_in[9];
    const float* b3  = (const float*)d_in[10];
    float* out = (float*)d_out;

    int B = in_sizes[0] / ZDIM;
    dim3 grid(ZDIM, (B + BTILE - 1) / BTILE);   // 64 x 32
    actor_mlp_kernel<<<grid, 256>>>(x, W1, b1, g1, be1, W2, b2, g2, be2,
                                    W3, b3, out, B);
}